// round 10
// baseline (speedup 1.0000x reference)
#include <cuda_runtime.h>

// Problem constants
#define NB   16      // batch
#define CI   128     // in channels
#define CO   256     // out channels
#define TT   128     // time
#define VV   25      // joints
#define WW   11      // parts
#define KG   3       // graph kernels
#define GG   8       // groups
#define MM   2048    // NB*TT
#define KK   3200    // VV*CI
#define NN   2816    // CO*WW
#define BN_EPS 1e-5f

// Scratch (static device globals — allocation-free contract)
__device__ float g_Xs[(size_t)MM * KK];     // 26 MB : x transposed to [(n,t), (v,i)]
__device__ float g_Wtot[(size_t)KK * NN];   // 36 MB : fused weight [(v,i), (c,w)]
__device__ float g_Btot[NN];                // fused bias

// ---------------------------------------------------------------------------
// Build Wtot[(v,i),(c,w)] = s_b[c]*sum_k A[k,c%8,v,w]*conv_w[k*CO+c,i]
//                         + sum_k RG[k,c%8,v,w]*s_d[o]*down_w[o,i]
// ---------------------------------------------------------------------------
__global__ void prep_w(const float* __restrict__ A_adj, const float* __restrict__ resg,
                       const float* __restrict__ conv_w, const float* __restrict__ down_w,
                       const float* __restrict__ dbn_g, const float* __restrict__ dbn_v,
                       const float* __restrict__ bn_g, const float* __restrict__ bn_v) {
    int row = blockIdx.x;          // (v,i): row = v*128 + i
    int v = row >> 7;
    int i = row & 127;
    for (int j = threadIdx.x; j < NN; j += blockDim.x) {
        int c = j / WW;
        int w = j - c * WW;
        int g = c & 7;
        float sb = bn_g[c] * rsqrtf(bn_v[c] + BN_EPS);
        float acc = 0.f;
#pragma unroll
        for (int k = 0; k < KG; k++) {
            int o = k * CO + c;
            int ai = ((k * GG + g) * VV + v) * WW + w;
            float a  = A_adj[ai];
            float rg = resg[ai];
            float sd = dbn_g[o] * rsqrtf(dbn_v[o] + BN_EPS);
            acc = fmaf(sb * a,  conv_w[o * CI + i], acc);
            acc = fmaf(rg * sd, down_w[o * CI + i], acc);
        }
        g_Wtot[(size_t)row * NN + j] = acc;
    }
}

// ---------------------------------------------------------------------------
// Btot[(c,w)] = s_b[c]*(sum_{k,v} A*conv_b[o]) + t_b[c] + sum_{k,v} RG*(down_b'[o])
// ---------------------------------------------------------------------------
__global__ void prep_b(const float* __restrict__ A_adj, const float* __restrict__ resg,
                       const float* __restrict__ conv_b, const float* __restrict__ down_b,
                       const float* __restrict__ dbn_g, const float* __restrict__ dbn_b,
                       const float* __restrict__ dbn_m, const float* __restrict__ dbn_v,
                       const float* __restrict__ bn_g, const float* __restrict__ bn_b,
                       const float* __restrict__ bn_m, const float* __restrict__ bn_v) {
    int j = blockIdx.x * blockDim.x + threadIdx.x;
    if (j >= NN) return;
    int c = j / WW;
    int w = j - c * WW;
    int g = c & 7;
    float sb = bn_g[c] * rsqrtf(bn_v[c] + BN_EPS);
    float tb = bn_b[c] - bn_m[c] * sb;
    float acc = tb;
#pragma unroll
    for (int k = 0; k < KG; k++) {
        int o = k * CO + c;
        float sd  = dbn_g[o] * rsqrtf(dbn_v[o] + BN_EPS);
        float td  = dbn_b[o] - dbn_m[o] * sd;
        float dbp = down_b[o] * sd + td;       // folded residual bias
        float cbs = sb * conv_b[o];            // folded main bias (bn scale applied)
        for (int v = 0; v < VV; v++) {
            int ai = ((k * GG + g) * VV + v) * WW + w;
            acc = fmaf(A_adj[ai], cbs, acc);
            acc = fmaf(resg[ai],  dbp, acc);
        }
    }
    g_Btot[j] = acc;
}

// ---------------------------------------------------------------------------
// Xs[(n*T+t)*KK + v*128 + i] = x[n,i,t,v]   (smem-tiled transpose)
// Block: fixed n, 4 t's, 32 i's, all 25 v's.
// ---------------------------------------------------------------------------
__global__ void transpose_x(const float* __restrict__ x) {
    __shared__ float s[32][101];   // padded: conflict-free on stride-100 reads
    int b  = blockIdx.x;
    int ib = b & 3;                // i block (4 x 32)
    int tb = (b >> 2) & 31;        // t block (32 x 4)
    int n  = b >> 7;
    int i0 = ib * 32;
    int t0 = tb * 4;
    const float* xp = x + (size_t)n * CI * TT * VV + (size_t)i0 * TT * VV + (size_t)t0 * VV;
    // load: per i-row, 100 contiguous floats (4 t's x 25 v's)
    for (int f = threadIdx.x; f < 3200; f += blockDim.x) {
        int il = f / 100;
        int q  = f - il * 100;
        s[il][q] = xp[(size_t)il * (TT * VV) + q];
    }
    __syncthreads();
    float* op = g_Xs + (size_t)(n * TT + t0) * KK + i0;
    // store: per (t,v), 32 contiguous i's
    for (int f = threadIdx.x; f < 3200; f += blockDim.x) {
        int tl = f / 800;
        int r  = f - tl * 800;
        int v  = r >> 5;
        int il = r & 31;
        op[(size_t)tl * KK + v * 128 + il] = s[il][tl * VV + v];
    }
}

// ---------------------------------------------------------------------------
// SGEMM 128x128x8, 256 threads, 8x8 per thread.
// C[m=(n,t), j=(c,w)] = relu( A[m,:] . B[:,j] + Btot[j] ), scattered to NCHW out.
// ---------------------------------------------------------------------------
__global__ __launch_bounds__(256) void gemm_relu(float* __restrict__ out) {
    __shared__ float As[8][128];
    __shared__ float Bs[8][128];
    const int m0 = blockIdx.y * 128;
    const int n0 = blockIdx.x * 128;
    const int tid = threadIdx.x;
    const int ty = tid >> 4, tx = tid & 15;
    const int rowB = ty * 8, colB = tx * 8;

    const int a_r = tid >> 1, a_c = (tid & 1) * 4;   // A tile: 128 rows x 8 cols
    const int b_r = tid >> 5, b_c = (tid & 31) * 4;  // B tile: 8 rows x 128 cols
    const float* Aptr = g_Xs  + (size_t)(m0 + a_r) * KK + a_c;
    const float* Bptr = g_Wtot + (size_t)b_r * NN + n0 + b_c;

    float acc[8][8];
#pragma unroll
    for (int r = 0; r < 8; r++)
#pragma unroll
        for (int c = 0; c < 8; c++) acc[r][c] = 0.f;

    for (int k0 = 0; k0 < KK; k0 += 8) {
        float4 av = *(const float4*)(Aptr + k0);
        As[a_c + 0][a_r] = av.x;
        As[a_c + 1][a_r] = av.y;
        As[a_c + 2][a_r] = av.z;
        As[a_c + 3][a_r] = av.w;
        float4 bv = *(const float4*)(Bptr + (size_t)k0 * NN);
        *(float4*)&Bs[b_r][b_c] = bv;
        __syncthreads();
#pragma unroll
        for (int kk = 0; kk < 8; kk++) {
            float a[8], b[8];
#pragma unroll
            for (int r = 0; r < 8; r++) a[r] = As[kk][rowB + r];
#pragma unroll
            for (int c = 0; c < 8; c++) b[c] = Bs[kk][colB + c];
#pragma unroll
            for (int r = 0; r < 8; r++)
#pragma unroll
                for (int c = 0; c < 8; c++) acc[r][c] = fmaf(a[r], b[c], acc[r][c]);
        }
        __syncthreads();
    }

    // epilogue: bias + relu + scatter to out[n, c, t, w]
#pragma unroll
    for (int cc = 0; cc < 8; cc++) {
        int j = n0 + colB + cc;
        int c = j / WW;
        int w = j - c * WW;
        float bb = g_Btot[j];
        size_t obase = (size_t)c * (TT * WW) + w;
#pragma unroll
        for (int r = 0; r < 8; r++) {
            int m = m0 + rowB + r;
            int n = m >> 7;
            int t = m & 127;
            float val = acc[r][cc] + bb;
            out[(size_t)n * (CO * TT * WW) + obase + (size_t)t * WW] = fmaxf(val, 0.f);
        }
    }
}

// ---------------------------------------------------------------------------
extern "C" void kernel_launch(void* const* d_in, const int* in_sizes, int n_in,
                              void* d_out, int out_size) {
    const float* x      = (const float*)d_in[0];
    const float* A_adj  = (const float*)d_in[1];
    const float* resg   = (const float*)d_in[2];
    const float* conv_w = (const float*)d_in[3];
    const float* conv_b = (const float*)d_in[4];
    const float* down_w = (const float*)d_in[5];
    const float* down_b = (const float*)d_in[6];
    const float* dbn_g  = (const float*)d_in[7];
    const float* dbn_b  = (const float*)d_in[8];
    const float* dbn_m  = (const float*)d_in[9];
    const float* dbn_v  = (const float*)d_in[10];
    const float* bn_g   = (const float*)d_in[11];
    const float* bn_b   = (const float*)d_in[12];
    const float* bn_m   = (const float*)d_in[13];
    const float* bn_v   = (const float*)d_in[14];
    float* out = (float*)d_out;

    prep_w<<<KK, 256>>>(A_adj, resg, conv_w, down_w, dbn_g, dbn_v, bn_g, bn_v);
    prep_b<<<(NN + 255) / 256, 256>>>(A_adj, resg, conv_b, down_b,
                                      dbn_g, dbn_b, dbn_m, dbn_v,
                                      bn_g, bn_b, bn_m, bn_v);
    transpose_x<<<2048, 256>>>(x);
    dim3 grid(NN / 128, MM / 128);   // 22 x 16
    gemm_relu<<<grid, 256>>>(out);
}

// round 16
// speedup vs baseline: 2.4812x; 2.4812x over previous
#include <cuda_runtime.h>
#include <cuda_bf16.h>
#include <stdint.h>
#include <stddef.h>

// Problem constants
#define NB   16
#define CI   128
#define CO   256
#define TT   128
#define VV   25
#define WW   11
#define KG   3
#define MM   2048            // NB*TT
#define KK   3200            // VV*CI
#define NN   2816            // CO*WW
#define BN_EPS 1e-5f

// GEMM tiling
#define BM     128
#define BN     128
#define BK     64            // bf16 -> 128B rows (full XOR swizzle)
#define NSTAGE 3
#define SEGC   (KK / BK)     // 50 iters per segment
#define ITERS  (3 * SEGC)    // 150 (hi*hi | lo*hi | hi*lo)

#define A_STAGE_BYTES (BM * BK * 2)          // 16384
#define B_STAGE_BYTES (BN * BK * 2)          // 16384
#define STAGE_BYTES   (A_STAGE_BYTES + B_STAGE_BYTES)
#define SMEM_TOTAL    (NSTAGE * STAGE_BYTES) // 98304

// Scratch (allocation-free contract: static device globals)
__device__ __align__(1024) __nv_bfloat16 g_Xhi[(size_t)MM * KK];   // 13.1 MB
__device__ __align__(1024) __nv_bfloat16 g_Xlo[(size_t)MM * KK];   // 13.1 MB
__device__ __align__(1024) __nv_bfloat16 g_Whi[(size_t)NN * KK];   // 18.0 MB  [N, K] k-contig
__device__ __align__(1024) __nv_bfloat16 g_Wlo[(size_t)NN * KK];   // 18.0 MB
__device__ float g_Btot[NN];

// ---------------------------------------------------------------------------
// helpers
// ---------------------------------------------------------------------------
__device__ __forceinline__ uint32_t smem_u32(const void* p) {
    uint32_t a;
    asm("{ .reg .u64 t; cvta.to.shared.u64 t, %1; cvt.u32.u64 %0, t; }" : "=r"(a) : "l"(p));
    return a;
}
__device__ __forceinline__ void cp_async16(uint32_t dst, const void* src) {
    asm volatile("cp.async.cg.shared.global [%0], [%1], 16;" :: "r"(dst), "l"(src) : "memory");
}
__device__ __forceinline__ void cp_commit() {
    asm volatile("cp.async.commit_group;" ::: "memory");
}
__device__ __forceinline__ void cp_wait1() {
    asm volatile("cp.async.wait_group 1;" ::: "memory");
}
__device__ __forceinline__ void ldsm_x4(uint32_t* r, uint32_t addr) {
    asm volatile("ldmatrix.sync.aligned.m8n8.x4.shared.b16 {%0,%1,%2,%3}, [%4];"
                 : "=r"(r[0]), "=r"(r[1]), "=r"(r[2]), "=r"(r[3]) : "r"(addr));
}
__device__ __forceinline__ void mma16816(float* c, const uint32_t* a, uint32_t b0, uint32_t b1) {
    asm volatile(
        "mma.sync.aligned.m16n8k16.row.col.f32.bf16.bf16.f32 "
        "{%0,%1,%2,%3}, {%4,%5,%6,%7}, {%8,%9}, {%0,%1,%2,%3};"
        : "+f"(c[0]), "+f"(c[1]), "+f"(c[2]), "+f"(c[3])
        : "r"(a[0]), "r"(a[1]), "r"(a[2]), "r"(a[3]), "r"(b0), "r"(b1));
}

// ---------------------------------------------------------------------------
// prep_w: Whi/Wlo[(c,w) row, (v,i) col] bf16 split of fused weight
// ---------------------------------------------------------------------------
__global__ void prep_w(const float* __restrict__ A_adj, const float* __restrict__ resg,
                       const float* __restrict__ conv_w, const float* __restrict__ down_w,
                       const float* __restrict__ dbn_g, const float* __restrict__ dbn_v,
                       const float* __restrict__ bn_g, const float* __restrict__ bn_v) {
    int j = blockIdx.x;                 // (c,w)
    int c = j / WW;
    int w = j - c * WW;
    int g = c & 7;
    __shared__ float cA[KG][VV], cR[KG][VV];
    if (threadIdx.x < KG * VV) {
        int k = threadIdx.x / VV, v = threadIdx.x - k * VV;
        int o = k * CO + c;
        int ai = ((k * 8 + g) * VV + v) * WW + w;
        float sb = bn_g[c] * rsqrtf(bn_v[c] + BN_EPS);
        float sd = dbn_g[o] * rsqrtf(dbn_v[o] + BN_EPS);
        cA[k][v] = sb * A_adj[ai];
        cR[k][v] = resg[ai] * sd;
    }
    __syncthreads();
    size_t base = (size_t)j * KK;
    for (int row = threadIdx.x; row < KK; row += blockDim.x) {
        int v = row >> 7, i = row & 127;
        float acc = 0.f;
#pragma unroll
        for (int k = 0; k < KG; k++) {
            int o = k * CO + c;
            acc = fmaf(cA[k][v], conv_w[o * CI + i], acc);
            acc = fmaf(cR[k][v], down_w[o * CI + i], acc);
        }
        __nv_bfloat16 h = __float2bfloat16(acc);
        g_Whi[base + row] = h;
        g_Wlo[base + row] = __float2bfloat16(acc - __bfloat162float(h));
    }
}

// ---------------------------------------------------------------------------
// prep_b: fused bias
// ---------------------------------------------------------------------------
__global__ void prep_b(const float* __restrict__ A_adj, const float* __restrict__ resg,
                       const float* __restrict__ conv_b, const float* __restrict__ down_b,
                       const float* __restrict__ dbn_g, const float* __restrict__ dbn_b,
                       const float* __restrict__ dbn_m, const float* __restrict__ dbn_v,
                       const float* __restrict__ bn_g, const float* __restrict__ bn_b,
                       const float* __restrict__ bn_m, const float* __restrict__ bn_v) {
    int j = blockIdx.x * blockDim.x + threadIdx.x;
    if (j >= NN) return;
    int c = j / WW;
    int w = j - c * WW;
    int g = c & 7;
    float sb = bn_g[c] * rsqrtf(bn_v[c] + BN_EPS);
    float acc = bn_b[c] - bn_m[c] * sb;
#pragma unroll
    for (int k = 0; k < KG; k++) {
        int o = k * CO + c;
        float sd  = dbn_g[o] * rsqrtf(dbn_v[o] + BN_EPS);
        float td  = dbn_b[o] - dbn_m[o] * sd;
        float dbp = down_b[o] * sd + td;
        float cbs = sb * conv_b[o];
        for (int v = 0; v < VV; v++) {
            int ai = ((k * 8 + g) * VV + v) * WW + w;
            acc = fmaf(A_adj[ai], cbs, acc);
            acc = fmaf(resg[ai],  dbp, acc);
        }
    }
    g_Btot[j] = acc;
}

// ---------------------------------------------------------------------------
// transpose_x: x[n,i,t,v] -> Xhi/Xlo[(n,t) row, v*128+i col] bf16 split
// ---------------------------------------------------------------------------
__global__ void transpose_x(const float* __restrict__ x) {
    __shared__ float s[32][101];
    int b  = blockIdx.x;
    int ib = b & 3;
    int tb = (b >> 2) & 31;
    int n  = b >> 7;
    int i0 = ib * 32;
    int t0 = tb * 4;
    const float* xp = x + (size_t)n * CI * TT * VV + (size_t)i0 * TT * VV + (size_t)t0 * VV;
    for (int f = threadIdx.x; f < 3200; f += blockDim.x) {
        int il = f / 100;
        int q  = f - il * 100;
        s[il][q] = xp[(size_t)il * (TT * VV) + q];
    }
    __syncthreads();
    size_t ob = (size_t)(n * TT + t0) * KK + i0;
    for (int f = threadIdx.x; f < 3200; f += blockDim.x) {
        int tl = f / 800;
        int r  = f - tl * 800;
        int v  = r >> 5;
        int il = r & 31;
        float val = s[il][tl * VV + v];
        __nv_bfloat16 h = __float2bfloat16(val);
        size_t idx = ob + (size_t)tl * KK + v * 128 + il;
        g_Xhi[idx] = h;
        g_Xlo[idx] = __float2bfloat16(val - __bfloat162float(h));
    }
}

// ---------------------------------------------------------------------------
// HMMA GEMM: C[2048, 2816], K' = 9600 (3-term bf16 split), bias+relu+scatter
// CTA 128x128, BK=64, 3-stage cp.async, 8 warps (64x32 warp tiles)
// ---------------------------------------------------------------------------
__global__ __launch_bounds__(256) void gemm_hmma(float* __restrict__ out) {
    extern __shared__ char smem[];
    const uint32_t sbase = smem_u32(smem);
    const int tid  = threadIdx.x;
    const int wid  = tid >> 5;
    const int lane = tid & 31;
    const int wm = wid & 1;          // 2 row groups of 64
    const int wn = wid >> 1;         // 4 col groups of 32
    const int m0 = blockIdx.y * BM;
    const int n0 = blockIdx.x * BN;

    // per-thread cp.async assignments: 8 x 16B chunks (4 for A, 4 for B)
    uint32_t sof[4];
    size_t   aoff[4], boff[4];
#pragma unroll
    for (int i = 0; i < 4; i++) {
        int l = tid + i * 256;       // 0..1023
        int r = l >> 3;              // row 0..127
        int c = l & 7;               // 16B chunk 0..7
        sof[i]  = r * 128 + ((c ^ (r & 7)) << 4);
        aoff[i] = (size_t)(m0 + r) * KK + c * 8;
        boff[i] = (size_t)(n0 + r) * KK + c * 8;
    }

    // ldmatrix source rows (per warp, fixed across iters)
    const int hi16 = lane >> 4;      // 0/1 -> k chunk select within k16
    uint32_t arow[4], brow[2];
#pragma unroll
    for (int mt = 0; mt < 4; mt++) {
        int r = wm * 64 + mt * 16 + (lane & 15);
        arow[mt] = r * 128 + 0;      // swizzle applied at use (needs r&7)
        arow[mt] |= (uint32_t)(r & 7) << 28;  // stash xor bits in high nibble
    }
#pragma unroll
    for (int p = 0; p < 2; p++) {
        int r = wn * 32 + p * 16 + (lane & 15);
        brow[p] = r * 128;
        brow[p] |= (uint32_t)(r & 7) << 28;
    }

    float acc[4][4][4];
#pragma unroll
    for (int mt = 0; mt < 4; mt++)
#pragma unroll
        for (int nt = 0; nt < 4; nt++)
#pragma unroll
            for (int q = 0; q < 4; q++) acc[mt][nt][q] = 0.f;

    // ---- pipeline ----
    auto issue = [&](int iter, int st) {
        int seg = iter / SEGC;
        int kk  = (iter - seg * SEGC) * BK;
        const __nv_bfloat16* Ab = (seg == 1) ? g_Xlo : g_Xhi;
        const __nv_bfloat16* Bb = (seg == 2) ? g_Wlo : g_Whi;
        uint32_t sa = sbase + st * STAGE_BYTES;
        uint32_t sbb = sa + A_STAGE_BYTES;
#pragma unroll
        for (int i = 0; i < 4; i++) {
            cp_async16(sa  + sof[i], Ab + aoff[i] + kk);
            cp_async16(sbb + sof[i], Bb + boff[i] + kk);
        }
    };

    issue(0, 0); cp_commit();
    issue(1, 1); cp_commit();

    for (int it = 0; it < ITERS; it++) {
        cp_wait1();
        __syncthreads();
        if (it + 2 < ITERS) issue(it + 2, (it + 2) % NSTAGE);
        cp_commit();

        const int st = it % NSTAGE;
        const uint32_t abase = sbase + st * STAGE_BYTES;
        const uint32_t bbase = abase + A_STAGE_BYTES;
#pragma unroll
        for (int ks = 0; ks < 4; ks++) {
            uint32_t af[4][4];
#pragma unroll
            for (int mt = 0; mt < 4; mt++) {
                uint32_t rw = arow[mt];
                uint32_t sx = rw >> 28;
                uint32_t c  = (uint32_t)(ks * 2 + hi16);
                ldsm_x4(af[mt], abase + (rw & 0x0FFFFFFF) + ((c ^ sx) << 4));
            }
            uint32_t bf[2][4];
#pragma unroll
            for (int p = 0; p < 2; p++) {
                uint32_t rw = brow[p];
                uint32_t sx = rw >> 28;
                uint32_t c  = (uint32_t)(ks * 2 + hi16);
                ldsm_x4(bf[p], bbase + (rw & 0x0FFFFFFF) + ((c ^ sx) << 4));
            }
#pragma unroll
            for (int mt = 0; mt < 4; mt++)
#pragma unroll
                for (int nt = 0; nt < 4; nt++) {
                    int p = nt >> 1, s = nt & 1;
                    mma16816(acc[mt][nt], af[mt], bf[p][s], bf[p][s + 2]);
                }
        }
        __syncthreads();
    }

    // ---- epilogue: bias + relu + NCHW scatter ----
#pragma unroll
    for (int mt = 0; mt < 4; mt++) {
        int mA = m0 + wm * 64 + mt * 16 + (lane >> 2);
        int mB = mA + 8;
        int nbA = mA >> 7, tA = mA & 127;
        int nbB = mB >> 7, tB = mB & 127;
        float* oA = out + (size_t)nbA * (CO * TT * WW) + (size_t)tA * WW;
        float* oB = out + (size_t)nbB * (CO * TT * WW) + (size_t)tB * WW;
#pragma unroll
        for (int nt = 0; nt < 4; nt++) {
            int j = n0 + wn * 32 + nt * 8 + (lane & 3) * 2;
            int c0 = j / WW,       w0 = j - c0 * WW;
            int c1 = (j + 1) / WW, w1 = (j + 1) - c1 * WW;
            float b0 = g_Btot[j], b1 = g_Btot[j + 1];
            oA[(size_t)c0 * (TT * WW) + w0] = fmaxf(acc[mt][nt][0] + b0, 0.f);
            oA[(size_t)c1 * (TT * WW) + w1] = fmaxf(acc[mt][nt][1] + b1, 0.f);
            oB[(size_t)c0 * (TT * WW) + w0] = fmaxf(acc[mt][nt][2] + b0, 0.f);
            oB[(size_t)c1 * (TT * WW) + w1] = fmaxf(acc[mt][nt][3] + b1, 0.f);
        }
    }
}

// ---------------------------------------------------------------------------
extern "C" void kernel_launch(void* const* d_in, const int* in_sizes, int n_in,
                              void* d_out, int out_size) {
    const float* x      = (const float*)d_in[0];
    const float* A_adj  = (const float*)d_in[1];
    const float* resg   = (const float*)d_in[2];
    const float* conv_w = (const float*)d_in[3];
    const float* conv_b = (const float*)d_in[4];
    const float* down_w = (const float*)d_in[5];
    const float* down_b = (const float*)d_in[6];
    const float* dbn_g  = (const float*)d_in[7];
    const float* dbn_b  = (const float*)d_in[8];
    const float* dbn_m  = (const float*)d_in[9];
    const float* dbn_v  = (const float*)d_in[10];
    const float* bn_g   = (const float*)d_in[11];
    const float* bn_b   = (const float*)d_in[12];
    const float* bn_m   = (const float*)d_in[13];
    const float* bn_v   = (const float*)d_in[14];
    float* out = (float*)d_out;

    static int smem_set = 0;
    if (!smem_set) {
        cudaFuncSetAttribute(gemm_hmma, cudaFuncAttributeMaxDynamicSharedMemorySize, SMEM_TOTAL);
        smem_set = 1;
    }

    prep_w<<<NN, 256>>>(A_adj, resg, conv_w, down_w, dbn_g, dbn_v, bn_g, bn_v);
    prep_b<<<(NN + 255) / 256, 256>>>(A_adj, resg, conv_b, down_b,
                                      dbn_g, dbn_b, dbn_m, dbn_v,
                                      bn_g, bn_b, bn_m, bn_v);
    transpose_x<<<2048, 256>>>(x);
    dim3 grid(NN / BN, MM / BM);   // 22 x 16
    gemm_hmma<<<grid, 256, SMEM_TOTAL>>>(out);
}

// round 17
// speedup vs baseline: 2.6994x; 1.0879x over previous
#include <cuda_runtime.h>
#include <cuda_bf16.h>
#include <stdint.h>
#include <stddef.h>

// Problem constants
#define NB   16
#define CI   128
#define CO   256
#define TT   128
#define VV   25
#define WW   11
#define KG   3
#define MM   2048            // NB*TT
#define KK   3200            // VV*CI
#define NN   2816            // CO*WW
#define BN_EPS 1e-5f

// GEMM tiling
#define BM     128
#define BN     128
#define BK     64            // bf16 -> 128B rows (full XOR swizzle)
#define NSTAGE 4
#define SEGC   (KK / BK)     // 50 iters per segment
#define ITERS  (3 * SEGC)    // 150 (hi*hi | lo*hi | hi*lo)

#define A_STAGE_BYTES (BM * BK * 2)          // 16384
#define B_STAGE_BYTES (BN * BK * 2)          // 16384
#define STAGE_BYTES   (A_STAGE_BYTES + B_STAGE_BYTES)
#define SMEM_TOTAL    (NSTAGE * STAGE_BYTES) // 131072

// Scratch (allocation-free contract: static device globals)
__device__ __align__(1024) __nv_bfloat16 g_Xhi[(size_t)MM * KK];   // 13.1 MB
__device__ __align__(1024) __nv_bfloat16 g_Xlo[(size_t)MM * KK];   // 13.1 MB
__device__ __align__(1024) __nv_bfloat16 g_Whi[(size_t)NN * KK];   // 18.0 MB  [N, K] k-contig
__device__ __align__(1024) __nv_bfloat16 g_Wlo[(size_t)NN * KK];   // 18.0 MB
__device__ float g_Btot[NN];

// ---------------------------------------------------------------------------
// helpers
// ---------------------------------------------------------------------------
__device__ __forceinline__ uint32_t smem_u32(const void* p) {
    uint32_t a;
    asm("{ .reg .u64 t; cvta.to.shared.u64 t, %1; cvt.u32.u64 %0, t; }" : "=r"(a) : "l"(p));
    return a;
}
__device__ __forceinline__ void cp_async16(uint32_t dst, const void* src) {
    asm volatile("cp.async.cg.shared.global [%0], [%1], 16;" :: "r"(dst), "l"(src) : "memory");
}
__device__ __forceinline__ void cp_commit() {
    asm volatile("cp.async.commit_group;" ::: "memory");
}
__device__ __forceinline__ void cp_wait2() {
    asm volatile("cp.async.wait_group %0;" :: "n"(NSTAGE - 2) : "memory");
}
__device__ __forceinline__ void ldsm_x4(uint32_t* r, uint32_t addr) {
    asm volatile("ldmatrix.sync.aligned.m8n8.x4.shared.b16 {%0,%1,%2,%3}, [%4];"
                 : "=r"(r[0]), "=r"(r[1]), "=r"(r[2]), "=r"(r[3]) : "r"(addr));
}
__device__ __forceinline__ void mma16816(float* c, const uint32_t* a, uint32_t b0, uint32_t b1) {
    asm volatile(
        "mma.sync.aligned.m16n8k16.row.col.f32.bf16.bf16.f32 "
        "{%0,%1,%2,%3}, {%4,%5,%6,%7}, {%8,%9}, {%0,%1,%2,%3};"
        : "+f"(c[0]), "+f"(c[1]), "+f"(c[2]), "+f"(c[3])
        : "r"(a[0]), "r"(a[1]), "r"(a[2]), "r"(a[3]), "r"(b0), "r"(b1));
}

// ---------------------------------------------------------------------------
// prep_w: Whi/Wlo[(c,w) row, (v,i) col] bf16 split of fused weight
// ---------------------------------------------------------------------------
__global__ void prep_w(const float* __restrict__ A_adj, const float* __restrict__ resg,
                       const float* __restrict__ conv_w, const float* __restrict__ down_w,
                       const float* __restrict__ dbn_g, const float* __restrict__ dbn_v,
                       const float* __restrict__ bn_g, const float* __restrict__ bn_v) {
    int j = blockIdx.x;                 // (c,w)
    int c = j / WW;
    int w = j - c * WW;
    int g = c & 7;
    __shared__ float cA[KG][VV], cR[KG][VV];
    if (threadIdx.x < KG * VV) {
        int k = threadIdx.x / VV, v = threadIdx.x - k * VV;
        int o = k * CO + c;
        int ai = ((k * 8 + g) * VV + v) * WW + w;
        float sb = bn_g[c] * rsqrtf(bn_v[c] + BN_EPS);
        float sd = dbn_g[o] * rsqrtf(dbn_v[o] + BN_EPS);
        cA[k][v] = sb * A_adj[ai];
        cR[k][v] = resg[ai] * sd;
    }
    __syncthreads();
    size_t base = (size_t)j * KK;
    for (int row = threadIdx.x; row < KK; row += blockDim.x) {
        int v = row >> 7, i = row & 127;
        float acc = 0.f;
#pragma unroll
        for (int k = 0; k < KG; k++) {
            int o = k * CO + c;
            acc = fmaf(cA[k][v], conv_w[o * CI + i], acc);
            acc = fmaf(cR[k][v], down_w[o * CI + i], acc);
        }
        __nv_bfloat16 h = __float2bfloat16(acc);
        g_Whi[base + row] = h;
        g_Wlo[base + row] = __float2bfloat16(acc - __bfloat162float(h));
    }
}

// ---------------------------------------------------------------------------
// prep_b: fused bias
// ---------------------------------------------------------------------------
__global__ void prep_b(const float* __restrict__ A_adj, const float* __restrict__ resg,
                       const float* __restrict__ conv_b, const float* __restrict__ down_b,
                       const float* __restrict__ dbn_g, const float* __restrict__ dbn_b,
                       const float* __restrict__ dbn_m, const float* __restrict__ dbn_v,
                       const float* __restrict__ bn_g, const float* __restrict__ bn_b,
                       const float* __restrict__ bn_m, const float* __restrict__ bn_v) {
    int j = blockIdx.x * blockDim.x + threadIdx.x;
    if (j >= NN) return;
    int c = j / WW;
    int w = j - c * WW;
    int g = c & 7;
    float sb = bn_g[c] * rsqrtf(bn_v[c] + BN_EPS);
    float acc = bn_b[c] - bn_m[c] * sb;
#pragma unroll
    for (int k = 0; k < KG; k++) {
        int o = k * CO + c;
        float sd  = dbn_g[o] * rsqrtf(dbn_v[o] + BN_EPS);
        float td  = dbn_b[o] - dbn_m[o] * sd;
        float dbp = down_b[o] * sd + td;
        float cbs = sb * conv_b[o];
        for (int v = 0; v < VV; v++) {
            int ai = ((k * 8 + g) * VV + v) * WW + w;
            acc = fmaf(A_adj[ai], cbs, acc);
            acc = fmaf(resg[ai],  dbp, acc);
        }
    }
    g_Btot[j] = acc;
}

// ---------------------------------------------------------------------------
// transpose_x: x[n,i,t,v] -> Xhi/Xlo[(n,t) row, v*128+i col] bf16 split
// ---------------------------------------------------------------------------
__global__ void transpose_x(const float* __restrict__ x) {
    __shared__ float s[32][101];
    int b  = blockIdx.x;
    int ib = b & 3;
    int tb = (b >> 2) & 31;
    int n  = b >> 7;
    int i0 = ib * 32;
    int t0 = tb * 4;
    const float* xp = x + (size_t)n * CI * TT * VV + (size_t)i0 * TT * VV + (size_t)t0 * VV;
    for (int f = threadIdx.x; f < 3200; f += blockDim.x) {
        int il = f / 100;
        int q  = f - il * 100;
        s[il][q] = xp[(size_t)il * (TT * VV) + q];
    }
    __syncthreads();
    size_t ob = (size_t)(n * TT + t0) * KK + i0;
    for (int f = threadIdx.x; f < 3200; f += blockDim.x) {
        int tl = f / 800;
        int r  = f - tl * 800;
        int v  = r >> 5;
        int il = r & 31;
        float val = s[il][tl * VV + v];
        __nv_bfloat16 h = __float2bfloat16(val);
        size_t idx = ob + (size_t)tl * KK + v * 128 + il;
        g_Xhi[idx] = h;
        g_Xlo[idx] = __float2bfloat16(val - __bfloat162float(h));
    }
}

// ---------------------------------------------------------------------------
// HMMA GEMM: C[2048, 2816], K' = 9600 (3-term bf16 split), bias+relu+scatter
// CTA 128x128, BK=64, 4-stage cp.async, single barrier per iter,
// register double-buffered ldmatrix fragments. 8 warps (64x32 warp tiles).
// ---------------------------------------------------------------------------
__global__ __launch_bounds__(256) void gemm_hmma(float* __restrict__ out) {
    extern __shared__ char smem[];
    const uint32_t sbase = smem_u32(smem);
    const int tid  = threadIdx.x;
    const int wid  = tid >> 5;
    const int lane = tid & 31;
    const int wm = wid & 1;          // 2 row groups of 64
    const int wn = wid >> 1;         // 4 col groups of 32
    const int m0 = blockIdx.y * BM;
    const int n0 = blockIdx.x * BN;

    // per-thread cp.async assignments: 8 x 16B chunks (4 for A, 4 for B)
    uint32_t sof[4];
    size_t   aoff[4], boff[4];
#pragma unroll
    for (int i = 0; i < 4; i++) {
        int l = tid + i * 256;       // 0..1023
        int r = l >> 3;              // row 0..127
        int c = l & 7;               // 16B chunk 0..7
        sof[i]  = r * 128 + ((c ^ (r & 7)) << 4);
        aoff[i] = (size_t)(m0 + r) * KK + c * 8;
        boff[i] = (size_t)(n0 + r) * KK + c * 8;
    }

    // ldmatrix source rows (per warp, fixed across iters); xor bits stashed high
    const uint32_t hi16 = lane >> 4;
    uint32_t arow[4], brow[2];
#pragma unroll
    for (int mt = 0; mt < 4; mt++) {
        int r = wm * 64 + mt * 16 + (lane & 15);
        arow[mt] = (uint32_t)(r * 128) | ((uint32_t)(r & 7) << 28);
    }
#pragma unroll
    for (int p = 0; p < 2; p++) {
        int r = wn * 32 + p * 16 + (lane & 15);
        brow[p] = (uint32_t)(r * 128) | ((uint32_t)(r & 7) << 28);
    }

    float acc[4][4][4];
#pragma unroll
    for (int mt = 0; mt < 4; mt++)
#pragma unroll
        for (int nt = 0; nt < 4; nt++)
#pragma unroll
            for (int q = 0; q < 4; q++) acc[mt][nt][q] = 0.f;

    auto issue = [&](int iter) {
        int st  = iter % NSTAGE;
        int seg = iter / SEGC;
        int kk  = (iter - seg * SEGC) * BK;
        const __nv_bfloat16* Ab = (seg == 1) ? g_Xlo : g_Xhi;
        const __nv_bfloat16* Bb = (seg == 2) ? g_Wlo : g_Whi;
        uint32_t sa  = sbase + st * STAGE_BYTES;
        uint32_t sbb = sa + A_STAGE_BYTES;
#pragma unroll
        for (int i = 0; i < 4; i++) {
            cp_async16(sa  + sof[i], Ab + aoff[i] + kk);
            cp_async16(sbb + sof[i], Bb + boff[i] + kk);
        }
    };

    // double-buffered fragments
    uint32_t af[2][4][4];
    uint32_t bf[2][2][4];
    auto load_frags = [&](int ks, int buf, uint32_t abase, uint32_t bbase) {
        uint32_t c = (uint32_t)(ks * 2) + hi16;
#pragma unroll
        for (int mt = 0; mt < 4; mt++) {
            uint32_t rw = arow[mt];
            ldsm_x4(af[buf][mt], abase + (rw & 0x0FFFFFFF) + (((c) ^ (rw >> 28)) << 4));
        }
#pragma unroll
        for (int p = 0; p < 2; p++) {
            uint32_t rw = brow[p];
            ldsm_x4(bf[buf][p], bbase + (rw & 0x0FFFFFFF) + (((c) ^ (rw >> 28)) << 4));
        }
    };

    // prologue: fill stages 0..NSTAGE-2
#pragma unroll
    for (int s = 0; s < NSTAGE - 1; s++) { issue(s); cp_commit(); }
    cp_wait2();            // stage 0 resident
    __syncthreads();

    for (int it = 0; it < ITERS; it++) {
        const int st = it % NSTAGE;
        const uint32_t abase = sbase + st * STAGE_BYTES;
        const uint32_t bbase = abase + A_STAGE_BYTES;

        load_frags(0, 0, abase, bbase);
        // issue stage it+NSTAGE-1 (aliases stage read in iter it-1; safe after barrier)
        if (it + NSTAGE - 1 < ITERS) issue(it + NSTAGE - 1);
        cp_commit();

#pragma unroll
        for (int ks = 0; ks < 4; ks++) {
            const int cur = ks & 1;
            if (ks < 3) load_frags(ks + 1, cur ^ 1, abase, bbase);
#pragma unroll
            for (int mt = 0; mt < 4; mt++)
#pragma unroll
                for (int nt = 0; nt < 4; nt++) {
                    int p = nt >> 1, s = nt & 1;
                    mma16816(acc[mt][nt], af[cur][mt], bf[cur][p][s], bf[cur][p][s + 2]);
                }
        }

        cp_wait2();        // stage it+1 resident
        __syncthreads();   // single barrier per iteration
    }

    // ---- epilogue: bias + relu + NCHW scatter ----
#pragma unroll
    for (int mt = 0; mt < 4; mt++) {
        int mA = m0 + wm * 64 + mt * 16 + (lane >> 2);
        int mB = mA + 8;
        int nbA = mA >> 7, tA = mA & 127;
        int nbB = mB >> 7, tB = mB & 127;
        float* oA = out + (size_t)nbA * (CO * TT * WW) + (size_t)tA * WW;
        float* oB = out + (size_t)nbB * (CO * TT * WW) + (size_t)tB * WW;
#pragma unroll
        for (int nt = 0; nt < 4; nt++) {
            int j = n0 + wn * 32 + nt * 8 + (lane & 3) * 2;
            int c0 = j / WW,       w0 = j - c0 * WW;
            int c1 = (j + 1) / WW, w1 = (j + 1) - c1 * WW;
            float b0 = g_Btot[j], b1 = g_Btot[j + 1];
            oA[(size_t)c0 * (TT * WW) + w0] = fmaxf(acc[mt][nt][0] + b0, 0.f);
            oA[(size_t)c1 * (TT * WW) + w1] = fmaxf(acc[mt][nt][1] + b1, 0.f);
            oB[(size_t)c0 * (TT * WW) + w0] = fmaxf(acc[mt][nt][2] + b0, 0.f);
            oB[(size_t)c1 * (TT * WW) + w1] = fmaxf(acc[mt][nt][3] + b1, 0.f);
        }
    }
}

// ---------------------------------------------------------------------------
extern "C" void kernel_launch(void* const* d_in, const int* in_sizes, int n_in,
                              void* d_out, int out_size) {
    const float* x      = (const float*)d_in[0];
    const float* A_adj  = (const float*)d_in[1];
    const float* resg   = (const float*)d_in[2];
    const float* conv_w = (const float*)d_in[3];
    const float* conv_b = (const float*)d_in[4];
    const float* down_w = (const float*)d_in[5];
    const float* down_b = (const float*)d_in[6];
    const float* dbn_g  = (const float*)d_in[7];
    const float* dbn_b  = (const float*)d_in[8];
    const float* dbn_m  = (const float*)d_in[9];
    const float* dbn_v  = (const float*)d_in[10];
    const float* bn_g   = (const float*)d_in[11];
    const float* bn_b   = (const float*)d_in[12];
    const float* bn_m   = (const float*)d_in[13];
    const float* bn_v   = (const float*)d_in[14];
    float* out = (float*)d_out;

    static int smem_set = 0;
    if (!smem_set) {
        cudaFuncSetAttribute(gemm_hmma, cudaFuncAttributeMaxDynamicSharedMemorySize, SMEM_TOTAL);
        smem_set = 1;
    }

    prep_w<<<NN, 256>>>(A_adj, resg, conv_w, down_w, dbn_g, dbn_v, bn_g, bn_v);
    prep_b<<<(NN + 255) / 256, 256>>>(A_adj, resg, conv_b, down_b,
                                      dbn_g, dbn_b, dbn_m, dbn_v,
                                      bn_g, bn_b, bn_m, bn_v);
    transpose_x<<<2048, 256>>>(x);
    dim3 grid(NN / BN, MM / BM);   // 22 x 16
    gemm_hmma<<<grid, 256, SMEM_TOTAL>>>(out);
}